// round 17
// baseline (speedup 1.0000x reference)
#include <cuda_runtime.h>
#include <math.h>

// MaskedNorm: B=8, T=4096, C=1024 fp32. PDL-chained:
// k1: dense read (UNCONDITIONAL y loads); masked rows -> partial sums,
//     unmasked rows -> copy to out
// k2: fold partials -> per-channel scale/shift  (PDL wait on k1)
// k3: normalize masked rows (prefetch 2 row-pairs before PDL wait)

#define CCH   1024
#define C4    (CCH / 4)      // 256 float4 per row
#define RTOT  32768          // B*T
#define R4TOT (RTOT / 4)     // 8192 row-quads
#define R2TOT (RTOT / 2)     // 16384 row-pairs
#define NBLK  296            // k1 blocks: 2/SM x 148 SMs (1024 thr each)
#define G3    2048           // k3 blocks: 16384/2048 = 8 iters exact
#define EPSF  1e-4f

__device__ __align__(16) float g_psum[NBLK][CCH];
__device__ __align__(16) float g_psq [NBLK][CCH];
__device__ int   g_pcnt[NBLK];
__device__ __align__(16) float g_scale[CCH];
__device__ __align__(16) float g_shift[CCH];

__device__ __forceinline__ void gdc_launch_dependents() {
    asm volatile("griddepcontrol.launch_dependents;" ::: "memory");
}
__device__ __forceinline__ void gdc_wait() {
    asm volatile("griddepcontrol.wait;" ::: "memory");
}

__device__ __forceinline__ void acc4(float4& s, float4& q, const float4 v) {
    s.x += v.x; s.y += v.y; s.z += v.z; s.w += v.w;
    q.x = fmaf(v.x, v.x, q.x);
    q.y = fmaf(v.y, v.y, q.y);
    q.z = fmaf(v.z, v.z, q.z);
    q.w = fmaf(v.w, v.w, q.w);
}

// ---------- k1: masked reduce + unmasked copy (dense, unconditional loads) ----------
__global__ __launch_bounds__(1024, 2)
void mn_main(const float4* __restrict__ y4, const int4* __restrict__ mask4,
             float4* __restrict__ out4) {
    __shared__ float4 ssum[4][256];
    __shared__ float4 ssq [4][256];
    __shared__ int    scnt[4];
    const int t = threadIdx.x & 255;   // channel slot (4 channels)
    const int g = threadIdx.x >> 8;    // row group 0..3
    const int p = blockIdx.x;

    float4 s = make_float4(0.f, 0.f, 0.f, 0.f);
    float4 q = make_float4(0.f, 0.f, 0.f, 0.f);
    int cnt = 0;

    for (int r4 = p * 4 + g; r4 < R4TOT; r4 += NBLK * 4) {
        const int  r  = r4 * 4;
        const int4 mk = __ldg(&mask4[r4]);
        // Unconditional loads: issue without waiting on the mask value.
        const float4 v0 = __ldg(&y4[(r + 0) * C4 + t]);
        const float4 v1 = __ldg(&y4[(r + 1) * C4 + t]);
        const float4 v2 = __ldg(&y4[(r + 2) * C4 + t]);
        const float4 v3 = __ldg(&y4[(r + 3) * C4 + t]);
        if (mk.x > 0) { acc4(s, q, v0); cnt++; } else __stcs(&out4[(r + 0) * C4 + t], v0);
        if (mk.y > 0) { acc4(s, q, v1); cnt++; } else __stcs(&out4[(r + 1) * C4 + t], v1);
        if (mk.z > 0) { acc4(s, q, v2); cnt++; } else __stcs(&out4[(r + 2) * C4 + t], v2);
        if (mk.w > 0) { acc4(s, q, v3); cnt++; } else __stcs(&out4[(r + 3) * C4 + t], v3);
    }
    ssum[g][t] = s;
    ssq [g][t] = q;
    if (t == 0) scnt[g] = cnt;   // identical across t within a group
    __syncthreads();

    if (g == 0) {
        float4 S = ssum[0][t], Q = ssq[0][t];
        #pragma unroll
        for (int i = 1; i < 4; i++) {
            const float4 a = ssum[i][t], b = ssq[i][t];
            S.x += a.x; S.y += a.y; S.z += a.z; S.w += a.w;
            Q.x += b.x; Q.y += b.y; Q.z += b.z; Q.w += b.w;
        }
        reinterpret_cast<float4*>(g_psum[p])[t] = S;
        reinterpret_cast<float4*>(g_psq [p])[t] = Q;
        if (t == 0) g_pcnt[p] = scnt[0] + scnt[1] + scnt[2] + scnt[3];
    }
    gdc_launch_dependents();   // partials for this block are written
}

// ---------- k2: fold partials -> scale/shift (32 blocks x 1024 thr, PDL) ----------
__global__ __launch_bounds__(1024, 2)
void mn_stats(const float* __restrict__ gamma, const float* __restrict__ beta) {
    __shared__ float sfs[32][33];
    __shared__ float sfq[32][33];
    __shared__ int   sn;
    const int lane = threadIdx.x & 31;
    const int w    = threadIdx.x >> 5;
    const int c    = blockIdx.x * 32 + lane;

    const float gm = __ldg(&gamma[c]);   // k1-independent: load before wait
    const float bt = __ldg(&beta[c]);

    gdc_wait();   // k1's partials now visible

    float s = 0.0f, q = 0.0f;
    for (int p = w; p < NBLK; p += 32) {
        s += g_psum[p][c];
        q += g_psq [p][c];
    }
    sfs[w][lane] = s;
    sfq[w][lane] = q;

    if (w == 0) {
        int n = 0;
        for (int p = lane; p < NBLK; p += 32) n += g_pcnt[p];
        #pragma unroll
        for (int o = 16; o; o >>= 1) n += __shfl_down_sync(0xffffffffu, n, o);
        if (lane == 0) sn = n;
    }
    __syncthreads();

    if (w == 0) {
        float S = 0.0f, Q = 0.0f;
        #pragma unroll
        for (int i = 0; i < 32; i++) { S += sfs[i][lane]; Q += sfq[i][lane]; }
        const float nf   = (float)sn;
        const float mean = S / nf;
        const float var  = (Q - S * S / nf) / (nf - 1.0f);
        const float sd   = sqrtf(var);
        const float sc   = gm / (sd + EPSF);
        g_scale[c] = sc;
        g_shift[c] = bt - mean * sc;   // out = fma(y, sc, shift)
    }
    __syncthreads();
    gdc_launch_dependents();   // scale/shift written
}

// ---------- k3: normalize masked rows (2-pair prefetch before PDL wait) ----------
__global__ __launch_bounds__(256, 8)
void mn_norm(const float4* __restrict__ y4, const int* __restrict__ mask,
             float4* __restrict__ out4) {
    const int t = threadIdx.x;

    // Prefetch first TWO row-pairs (k2-independent) to overlap k2 + PDL hop.
    const int ra = blockIdx.x * 2;           // iteration 0
    const int rb = (blockIdx.x + G3) * 2;    // iteration 1
    const int ma0 = __ldg(&mask[ra + 0]);
    const int ma1 = __ldg(&mask[ra + 1]);
    const int mb0 = __ldg(&mask[rb + 0]);
    const int mb1 = __ldg(&mask[rb + 1]);
    float4 a0, a1, b0, b1;
    if (ma0 > 0) a0 = __ldg(&y4[(ra + 0) * C4 + t]);
    if (ma1 > 0) a1 = __ldg(&y4[(ra + 1) * C4 + t]);
    if (mb0 > 0) b0 = __ldg(&y4[(rb + 0) * C4 + t]);
    if (mb1 > 0) b1 = __ldg(&y4[(rb + 1) * C4 + t]);

    gdc_wait();   // scale/shift now visible

    const float4 sc = reinterpret_cast<const float4*>(g_scale)[t];
    const float4 sh = reinterpret_cast<const float4*>(g_shift)[t];

    if (ma0 > 0) {
        a0.x = fmaf(a0.x, sc.x, sh.x); a0.y = fmaf(a0.y, sc.y, sh.y);
        a0.z = fmaf(a0.z, sc.z, sh.z); a0.w = fmaf(a0.w, sc.w, sh.w);
        __stcs(&out4[(ra + 0) * C4 + t], a0);
    }
    if (ma1 > 0) {
        a1.x = fmaf(a1.x, sc.x, sh.x); a1.y = fmaf(a1.y, sc.y, sh.y);
        a1.z = fmaf(a1.z, sc.z, sh.z); a1.w = fmaf(a1.w, sc.w, sh.w);
        __stcs(&out4[(ra + 1) * C4 + t], a1);
    }
    if (mb0 > 0) {
        b0.x = fmaf(b0.x, sc.x, sh.x); b0.y = fmaf(b0.y, sc.y, sh.y);
        b0.z = fmaf(b0.z, sc.z, sh.z); b0.w = fmaf(b0.w, sc.w, sh.w);
        __stcs(&out4[(rb + 0) * C4 + t], b0);
    }
    if (mb1 > 0) {
        b1.x = fmaf(b1.x, sc.x, sh.x); b1.y = fmaf(b1.y, sc.y, sh.y);
        b1.z = fmaf(b1.z, sc.z, sh.z); b1.w = fmaf(b1.w, sc.w, sh.w);
        __stcs(&out4[(rb + 1) * C4 + t], b1);
    }

    #pragma unroll 1
    for (int r2 = blockIdx.x + 2 * G3; r2 < R2TOT; r2 += G3) {
        const int r  = r2 * 2;
        const int m0 = __ldg(&mask[r + 0]);
        const int m1 = __ldg(&mask[r + 1]);
        if (m0 > 0) {
            float4 v = __ldg(&y4[(r + 0) * C4 + t]);
            v.x = fmaf(v.x, sc.x, sh.x); v.y = fmaf(v.y, sc.y, sh.y);
            v.z = fmaf(v.z, sc.z, sh.z); v.w = fmaf(v.w, sc.w, sh.w);
            __stcs(&out4[(r + 0) * C4 + t], v);
        }
        if (m1 > 0) {
            float4 v = __ldg(&y4[(r + 1) * C4 + t]);
            v.x = fmaf(v.x, sc.x, sh.x); v.y = fmaf(v.y, sc.y, sh.y);
            v.z = fmaf(v.z, sc.z, sh.z); v.w = fmaf(v.w, sc.w, sh.w);
            __stcs(&out4[(r + 1) * C4 + t], v);
        }
    }
}

extern "C" void kernel_launch(void* const* d_in, const int* in_sizes, int n_in,
                              void* d_out, int out_size) {
    const float* y     = (const float*)d_in[0];
    const int*   mask  = (const int*)  d_in[1];
    const float* gamma = (const float*)d_in[2];
    const float* beta  = (const float*)d_in[3];
    float*       out   = (float*)d_out;

    mn_main<<<NBLK, 1024>>>((const float4*)y, (const int4*)mask, (float4*)out);

    cudaLaunchAttribute attr;
    attr.id = cudaLaunchAttributeProgrammaticStreamSerialization;
    attr.val.programmaticStreamSerializationAllowed = 1;

    {
        cudaLaunchConfig_t cfg = {};
        cfg.gridDim  = dim3(32, 1, 1);
        cfg.blockDim = dim3(1024, 1, 1);
        cfg.attrs    = &attr;
        cfg.numAttrs = 1;
        cfg.stream   = 0;
        cudaLaunchKernelEx(&cfg, mn_stats, gamma, beta);
    }
    {
        cudaLaunchConfig_t cfg = {};
        cfg.gridDim  = dim3(G3, 1, 1);
        cfg.blockDim = dim3(256, 1, 1);
        cfg.attrs    = &attr;
        cfg.numAttrs = 1;
        cfg.stream   = 0;
        cudaLaunchKernelEx(&cfg, mn_norm, (const float4*)y, mask, (float4*)out);
    }
}